// round 1
// baseline (speedup 1.0000x reference)
#include <cuda_runtime.h>

#define Bn 8
#define An 100000
#define Kn 80
#define Mn 32
#define F4_PER_IMG (An * Kn / 4)   /* 2,000,000 float4 per image */
#define ITERS 4

// ---------------- device scratch (no allocations allowed) ----------------
__device__ signed char g_codes[(size_t)Bn * An];  // -1 = not positive, else assigned class
__device__ float g_cls_sum[Bn];
__device__ float g_reg_sum[Bn];
__device__ float g_num_pos[Bn];

// ---------------- fast MUFU intrinsics (force approx regardless of flags) ----
__device__ __forceinline__ float fast_ex2(float x) { float r; asm("ex2.approx.f32 %0, %1;" : "=f"(r) : "f"(x)); return r; }
__device__ __forceinline__ float fast_lg2(float x) { float r; asm("lg2.approx.f32 %0, %1;" : "=f"(r) : "f"(x)); return r; }
__device__ __forceinline__ float fast_rcp(float x) { float r; asm("rcp.approx.f32 %0, %1;" : "=f"(r) : "f"(x)); return r; }

// ---------------- init accumulators (graph replays need re-zeroing) ------
__global__ void init_kernel() {
    int t = threadIdx.x;
    if (t < Bn) { g_cls_sum[t] = 0.f; g_reg_sum[t] = 0.f; g_num_pos[t] = 0.f; }
}

// ---------------- kernel A: IoU assignment + regression loss -------------
__global__ void assign_kernel(const float* __restrict__ anchors,
                              const float* __restrict__ annotations,
                              const float* __restrict__ regressions) {
    __shared__ float bx1[Mn], by1[Mn], bx2[Mn], by2[Mn], barea[Mn], blab[Mn];
    __shared__ int   bval[Mn];
    const int b = blockIdx.y;
    const int t = threadIdx.x;
    if (t < Mn) {
        const float* ann = annotations + ((size_t)b * Mn + t) * 5;
        float x1 = ann[0], y1 = ann[1], x2 = ann[2], y2 = ann[3], lab = ann[4];
        bx1[t] = x1; by1[t] = y1; bx2[t] = x2; by2[t] = y2;
        barea[t] = (x2 - x1) * (y2 - y1);
        blab[t] = lab;
        bval[t] = (lab != -1.0f);
    }
    __syncthreads();

    const int a = blockIdx.x * blockDim.x + t;
    if (a >= An) return;

    const float ax1 = anchors[a * 4 + 0], ay1 = anchors[a * 4 + 1];
    const float ax2 = anchors[a * 4 + 2], ay2 = anchors[a * 4 + 3];
    const float areaA = (ax2 - ax1) * (ay2 - ay1);

    float best = -1e30f; int besti = 0;
    #pragma unroll
    for (int m = 0; m < Mn; m++) {
        float iou;
        if (bval[m]) {
            float iw = fminf(ax2, bx2[m]) - fmaxf(ax1, bx1[m]); iw = fmaxf(iw, 0.f);
            float ih = fminf(ay2, by2[m]) - fmaxf(ay1, by1[m]); ih = fmaxf(ih, 0.f);
            float inter = iw * ih;
            float ua = fmaxf(areaA + barea[m] - inter, 1e-8f);
            iou = inter / ua;   // IEEE div: threshold decisions (0.5, argmax) must match ref
        } else {
            iou = -1.0f;
        }
        if (iou > best) { best = iou; besti = m; }   // strictly-greater => first-max (jnp.argmax)
    }

    const bool pos = (best >= 0.5f);
    g_codes[(size_t)b * An + a] = pos ? (signed char)(int)blab[besti] : (signed char)(-1);

    if (pos) {
        atomicAdd(&g_num_pos[b], 1.0f);
        float aw = ax2 - ax1, ah = ay2 - ay1;
        float acx = ax1 + 0.5f * aw, acy = ay1 + 0.5f * ah;
        float gx1 = bx1[besti], gy1 = by1[besti], gx2 = bx2[besti], gy2 = by2[besti];
        float gw = gx2 - gx1, gh = gy2 - gy1;
        float gcx = gx1 + 0.5f * gw, gcy = gy1 + 0.5f * gh;
        gw = fmaxf(gw, 1.0f); gh = fmaxf(gh, 1.0f);
        float tt[4];
        tt[0] = ((gcx - acx) / aw) / 0.1f;
        tt[1] = ((gcy - acy) / ah) / 0.1f;
        tt[2] = logf(gw / aw) / 0.2f;
        tt[3] = logf(gh / ah) / 0.2f;
        const float* r = regressions + ((size_t)b * An + a) * 4;
        float s = 0.f;
        #pragma unroll
        for (int j = 0; j < 4; j++) {
            float d = fabsf(tt[j] - r[j]);
            float sl = (d <= (float)(1.0 / 9.0)) ? 4.5f * d * d : d - (float)(0.5 / 9.0);
            s += sl;
        }
        atomicAdd(&g_reg_sum[b], s);
    }
}

// ---------------- per-element focal loss ---------------------------------
// take1: loss = 0.25*(1-p)^2*softplus(-x)  = (0.25*ln2) * ((e/(1+e))^2) * lg2(1+e)
// else:  loss = 0.75*p^2*(x+softplus(-x))  = 0.75 * (1/(1+e))^2 * (x + ln2*lg2(1+e))
__device__ __forceinline__ float focal_elem(float c, bool take1) {
    float x = fminf(fmaxf(c, 1e-4f), 0.9999f);
    float e = fast_ex2(x * -1.44269504f);
    float q = 1.0f + e;
    float u = fast_rcp(q);     // p
    float l = fast_lg2(q);     // sp / ln2
    if (take1) {
        float omp = e * u;     // 1-p
        return 0.17328680f * (omp * omp) * l;          // 0.25*ln2
    } else {
        return 0.75f * (u * u) * fmaf(0.69314718f, l, x);
    }
}

// ---------------- kernel B: focal classification loss (HBM/MUFU bound) ----
__global__ void __launch_bounds__(256) focal_kernel(const float* __restrict__ cls) {
    const int b = blockIdx.y;
    const float4* __restrict__ src = (const float4*)cls + (size_t)b * F4_PER_IMG;
    const signed char* __restrict__ codes = g_codes + (size_t)b * An;

    float s = 0.f;
    const int base = blockIdx.x * (blockDim.x * ITERS) + threadIdx.x;
    #pragma unroll
    for (int it = 0; it < ITERS; it++) {
        int idx = base + it * 256;
        if (idx < F4_PER_IMG) {
            int anchor = idx / 20;               // 20 float4 per anchor (K=80)
            int k0 = (idx - anchor * 20) * 4;
            int code = codes[anchor];
            float4 v = src[idx];
            if (code < 0) {
                // common path: all four elements take branch-1 (no branch-2 math emitted)
                s += focal_elem(v.x, true);
                s += focal_elem(v.y, true);
                s += focal_elem(v.z, true);
                s += focal_elem(v.w, true);
            } else {
                s += focal_elem(v.x, k0 + 0 == code);
                s += focal_elem(v.y, k0 + 1 == code);
                s += focal_elem(v.z, k0 + 2 == code);
                s += focal_elem(v.w, k0 + 3 == code);
            }
        }
    }

    // block reduction
    #pragma unroll
    for (int o = 16; o > 0; o >>= 1) s += __shfl_down_sync(0xffffffffu, s, o);
    __shared__ float wsum[8];
    int lane = threadIdx.x & 31, w = threadIdx.x >> 5;
    if (lane == 0) wsum[w] = s;
    __syncthreads();
    if (threadIdx.x < 8) {
        float v = wsum[threadIdx.x];
        #pragma unroll
        for (int o = 4; o > 0; o >>= 1) v += __shfl_down_sync(0x000000ffu, v, o);
        if (threadIdx.x == 0) atomicAdd(&g_cls_sum[b], v);
    }
}

// ---------------- kernel C: finalize -------------------------------------
__global__ void final_kernel(const float* __restrict__ annotations,
                             float* __restrict__ out, int out_size) {
    int t = threadIdx.x;
    float cls = 0.f, reg = 0.f;
    if (t < Bn) {
        bool has = false;
        #pragma unroll
        for (int m = 0; m < Mn; m++)
            has = has || (annotations[((size_t)t * Mn + m) * 5 + 4] != -1.0f);
        float np = g_num_pos[t];
        float c = g_cls_sum[t] / fmaxf(np, 0.01f);
        float r = (np > 0.f) ? (g_reg_sum[t] / fmaxf(np * 4.0f, 1.0f)) : 0.f;
        if (has) { cls = c; reg = r; }
    }
    #pragma unroll
    for (int o = 16; o > 0; o >>= 1) {
        cls += __shfl_down_sync(0xffffffffu, cls, o);
        reg += __shfl_down_sync(0xffffffffu, reg, o);
    }
    if (t == 0) {
        out[0] = cls * (1.0f / (float)Bn);
        if (out_size > 1) out[1] = reg * (1.0f / (float)Bn);
    }
}

// ---------------- launch ---------------------------------------------------
extern "C" void kernel_launch(void* const* d_in, const int* in_sizes, int n_in,
                              void* d_out, int out_size) {
    const float *cls = nullptr, *reg = nullptr, *anc = nullptr, *ann = nullptr;
    for (int i = 0; i < n_in; i++) {
        long long sz = in_sizes[i];
        if      (sz == (long long)Bn * An * Kn) cls = (const float*)d_in[i];
        else if (sz == (long long)Bn * An * 4)  reg = (const float*)d_in[i];
        else if (sz == (long long)An * 4)       anc = (const float*)d_in[i];
        else if (sz == (long long)Bn * Mn * 5)  ann = (const float*)d_in[i];
    }

    init_kernel<<<1, 32>>>();

    dim3 ga((An + 255) / 256, Bn);
    assign_kernel<<<ga, 256>>>(anc, ann, reg);

    dim3 gf((F4_PER_IMG + 256 * ITERS - 1) / (256 * ITERS), Bn);
    focal_kernel<<<gf, 256>>>(cls);

    final_kernel<<<1, 32>>>(ann, (float*)d_out, out_size);
}